// round 13
// baseline (speedup 1.0000x reference)
#include <cuda_runtime.h>
#include <cuda_fp16.h>
#include <cstdint>

#define D        256
#define TM       64
#define NTH      256          // warps 0-3 consumers (MMA), 4-7 producers (gather)

#define ABUF     32768        // one A buffer: 64 rows x 512B
// smem layout (bytes)
#define SMEM_A0    0
#define SMEM_A1    32768
#define SMEM_SB1   65536      // 256 floats
#define SMEM_SB2   66560
#define SMEM_SW3   67584
#define SMEM_RED   68608      // 4 x 64 floats
#define SMEM_TOTAL 70656

// consumer-only barrier (warps 0-3 = threads 0-127)
#define CBAR() asm volatile("bar.sync 1, 128;" ::: "memory")

// frag-packed fp16 weights: [layer(2)][ktile(16)][slot(16)][lane(32)] x 16B
__device__ uint4 g_bpack[2 * 16 * 16 * 32];

__device__ __forceinline__ uint32_t f2h2(float lo, float hi) {
    __half2 h = __floats2half2_rn(lo, hi);
    return *(uint32_t*)&h;
}

__device__ __forceinline__ void mma_f16(float* c, const uint32_t* a, uint32_t b0, uint32_t b1) {
    asm volatile("mma.sync.aligned.m16n8k16.row.col.f32.f16.f16.f32 "
                 "{%0,%1,%2,%3}, {%4,%5,%6,%7}, {%8,%9}, {%0,%1,%2,%3};"
                 : "+f"(c[0]), "+f"(c[1]), "+f"(c[2]), "+f"(c[3])
                 : "r"(a[0]), "r"(a[1]), "r"(a[2]), "r"(a[3]), "r"(b0), "r"(b1));
}

// ------------------------------------------------------------- weight prep
__global__ void pack_w_kernel(const float* __restrict__ w1, const float* __restrict__ w2) {
    int idx = blockIdx.x * 256 + threadIdx.x;      // 16384 uint4 slots
    int l    = idx >> 13;
    int kt   = (idx >> 9) & 15;
    int s    = (idx >> 5) & 15;
    int lane = idx & 31;
    const float* w = l ? w2 : w1;
    int g = lane >> 2, t = lane & 3;
    int k0 = kt * 16 + 2 * t;
    int na = 16 * s + g;
    int nb = na + 8;
    uint4 v;
    v.x = f2h2(w[(k0    ) * D + na], w[(k0 + 1) * D + na]);
    v.y = f2h2(w[(k0 + 8) * D + na], w[(k0 + 9) * D + na]);
    v.z = f2h2(w[(k0    ) * D + nb], w[(k0 + 1) * D + nb]);
    v.w = f2h2(w[(k0 + 8) * D + nb], w[(k0 + 9) * D + nb]);
    g_bpack[idx] = v;
}

// A smem address: row-major fp16, 512B rows, 16B-unit swizzle (low 3 bits ^ row&7)
__device__ __forceinline__ uint32_t a_addr(uint32_t sbuf, int row, int unit) {
    return sbuf + row * 512 + ((((unsigned)unit & 24u) | (((unsigned)unit ^ (unsigned)(row & 7)) & 7u)) << 4);
}

// producer: gather 16 rows (warp-per-row, coalesced) into buffer sbuf
__device__ __forceinline__ void gather_tile(
    uint32_t sbuf, int m0, int rbase, int lane,
    const int* __restrict__ pv, const int* __restrict__ qv,
    const float* __restrict__ E, int M)
{
    #pragma unroll 4
    for (int rr = 0; rr < 16; ++rr) {
        int r  = rbase + rr;
        int gi = m0 + r;
        int pi = (gi < M) ? __ldg(pv + gi) : 0;
        int qi = (gi < M) ? __ldg(qv + gi) : 0;
        const float4* P = (const float4*)(E + (size_t)pi * D);
        const float4* Q = (const float4*)(E + (size_t)qi * D);
        float4 p0 = __ldg(P + lane), p1 = __ldg(P + 32 + lane);
        float4 q0 = __ldg(Q + lane), q1 = __ldg(Q + 32 + lane);
        float d0 = p0.x - q0.x, d1 = p0.y - q0.y, d2 = p0.z - q0.z, d3 = p0.w - q0.w;
        float e0 = p1.x - q1.x, e1 = p1.y - q1.y, e2 = p1.z - q1.z, e3 = p1.w - q1.w;
        uint32_t lo0 = f2h2(d0 * d0, d1 * d1);
        uint32_t lo1 = f2h2(d2 * d2, d3 * d3);
        uint32_t hi0 = f2h2(e0 * e0, e1 * e1);
        uint32_t hi1 = f2h2(e2 * e2, e3 * e3);
        uint32_t addr0 = a_addr(sbuf, r,      lane >> 1) + (lane & 1) * 8;
        uint32_t addr1 = a_addr(sbuf, r, 16 + (lane >> 1)) + (lane & 1) * 8;
        asm volatile("st.shared.v2.b32 [%0], {%1,%2};" :: "r"(addr0), "r"(lo0), "r"(lo1));
        asm volatile("st.shared.v2.b32 [%0], {%1,%2};" :: "r"(addr1), "r"(hi0), "r"(hi1));
    }
}

// ------------------------------------------------------------- main kernel
__global__ __launch_bounds__(NTH, 1)
void fused_mlp_mma(const int* __restrict__ pv, const int* __restrict__ qv,
                   const float* __restrict__ E,
                   const float* __restrict__ b1v, const float* __restrict__ b2v,
                   const float* __restrict__ w3v, const float* __restrict__ b3v,
                   float* __restrict__ out, int M)
{
    extern __shared__ char smem[];
    uint32_t sbA;
    asm("{ .reg .u64 u; cvta.to.shared.u64 u, %1; cvt.u32.u64 %0, u; }" : "=r"(sbA) : "l"(smem));
    const int t = threadIdx.x, lane = t & 31, wid = t >> 5;
    const int NTt = (M + TM - 1) / TM;

    float* sB1 = (float*)(smem + SMEM_SB1);
    float* sB2 = (float*)(smem + SMEM_SB2);
    float* sW3 = (float*)(smem + SMEM_SW3);
    sB1[t] = b1v[t]; sB2[t] = b2v[t]; sW3[t] = w3v[t];   // NTH == D

    int tile = blockIdx.x;
    int pb = 0;

    // prologue: producers fill buffer 0 for the first tile
    if (wid >= 4 && tile < NTt)
        gather_tile(sbA + SMEM_A0, tile * TM, (wid - 4) * 16, lane, pv, qv, E, M);
    __syncthreads();

    #pragma unroll 1
    for (; tile < NTt; tile += gridDim.x, pb ^= 1) {
        if (wid >= 4) {
            // ---------------- producers: gather NEXT tile into other buffer --
            int nxt = tile + gridDim.x;
            if (nxt < NTt)
                gather_tile(sbA + (pb ^ 1) * ABUF, nxt * TM, (wid - 4) * 16,
                            lane, pv, qv, E, M);
        } else {
            // ---------------- consumers: full MLP on current buffer ----------
            const uint32_t sbuf = sbA + pb * ABUF;
            const int wn = wid;                       // 0..3, tile 64x64
            const int m0 = tile * TM;

            float acc[4][8][4];
            #pragma unroll
            for (int m = 0; m < 4; ++m)
                #pragma unroll
                for (int n = 0; n < 8; ++n)
                    #pragma unroll
                    for (int e = 0; e < 4; ++e) acc[m][n][e] = 0.f;

            #pragma unroll 1
            for (int layer = 0; layer < 2; ++layer) {
                const uint4* bw = g_bpack + (size_t)layer * (16 * 16 * 32);
                uint4 bpre[2][4];
                #pragma unroll
                for (int pf = 0; pf < 2; ++pf)
                    #pragma unroll
                    for (int j = 0; j < 4; ++j)
                        bpre[pf][j] = __ldg(bw + ((pf * 16 + wn * 4 + j) * 32 + lane));

                #pragma unroll
                for (int ktl = 0; ktl < 16; ++ktl) {
                    uint4 bf[4];
                    #pragma unroll
                    for (int j = 0; j < 4; ++j) bf[j] = bpre[ktl & 1][j];
                    if (ktl + 2 < 16) {
                        #pragma unroll
                        for (int j = 0; j < 4; ++j)
                            bpre[ktl & 1][j] = __ldg(bw + (((ktl + 2) * 16 + wn * 4 + j) * 32 + lane));
                    }
                    #pragma unroll
                    for (int m = 0; m < 4; ++m) {
                        uint32_t a[4];
                        int row = m * 16 + (lane & 15);
                        uint32_t addr = a_addr(sbuf, row, ktl * 2 + (lane >> 4));
                        asm volatile("ldmatrix.sync.aligned.m8n8.x4.shared.b16 {%0,%1,%2,%3}, [%4];"
                                     : "=r"(a[0]), "=r"(a[1]), "=r"(a[2]), "=r"(a[3])
                                     : "r"(addr));
                        #pragma unroll
                        for (int j = 0; j < 4; ++j) {
                            mma_f16(acc[m][2 * j + 0], a, bf[j].x, bf[j].y);
                            mma_f16(acc[m][2 * j + 1], a, bf[j].z, bf[j].w);
                        }
                    }
                }

                if (layer == 0) {
                    CBAR();            // all consumers done reading layer-1 A
                    #pragma unroll
                    for (int m = 0; m < 4; ++m) {
                        int r0 = m * 16 + (lane >> 2);
                        #pragma unroll
                        for (int nt = 0; nt < 8; ++nt) {
                            int c0 = wn * 64 + nt * 8 + 2 * (lane & 3);
                            float v00 = fmaxf(acc[m][nt][0] + sB1[c0],     0.f);
                            float v01 = fmaxf(acc[m][nt][1] + sB1[c0 + 1], 0.f);
                            float v10 = fmaxf(acc[m][nt][2] + sB1[c0],     0.f);
                            float v11 = fmaxf(acc[m][nt][3] + sB1[c0 + 1], 0.f);
                            int u = wn * 8 + nt;
                            int off = (c0 & 7) * 2;
                            *(uint32_t*)((char*)smem + (a_addr(sbuf, r0,     u) - sbA) + off) = f2h2(v00, v01);
                            *(uint32_t*)((char*)smem + (a_addr(sbuf, r0 + 8, u) - sbA) + off) = f2h2(v10, v11);
                            acc[m][nt][0] = acc[m][nt][1] = acc[m][nt][2] = acc[m][nt][3] = 0.f;
                        }
                    }
                    CBAR();            // rewrite complete before layer-2 reads
                }
            }

            // ---- final: bias+relu, dot w3, reduce ---------------------------
            {
                float rsum[8];
                #pragma unroll
                for (int k = 0; k < 8; ++k) rsum[k] = 0.f;
                #pragma unroll
                for (int m = 0; m < 4; ++m)
                    #pragma unroll
                    for (int nt = 0; nt < 8; ++nt)
                        #pragma unroll
                        for (int h = 0; h < 2; ++h)
                            #pragma unroll
                            for (int e = 0; e < 2; ++e) {
                                int c = wn * 64 + nt * 8 + 2 * (lane & 3) + e;
                                float v = fmaxf(acc[m][nt][h * 2 + e] + sB2[c], 0.f);
                                rsum[m * 2 + h] = fmaf(v, sW3[c], rsum[m * 2 + h]);
                            }
                #pragma unroll
                for (int k = 0; k < 8; ++k) {
                    rsum[k] += __shfl_xor_sync(0xffffffffu, rsum[k], 1);
                    rsum[k] += __shfl_xor_sync(0xffffffffu, rsum[k], 2);
                }
                float* red = (float*)(smem + SMEM_RED);
                if ((lane & 3) == 0) {
                    #pragma unroll
                    for (int m = 0; m < 4; ++m)
                        #pragma unroll
                        for (int h = 0; h < 2; ++h)
                            red[wn * 64 + m * 16 + h * 8 + (lane >> 2)] = rsum[m * 2 + h];
                }
                CBAR();
                if (t < TM) {
                    int gi = m0 + t;
                    if (gi < M)
                        out[gi] = red[t] + red[64 + t] + red[128 + t] + red[192 + t] + __ldg(b3v);
                }
            }
        }
        __syncthreads();   // tile boundary: next buffer full, current one free
    }
}

// ------------------------------------------------------------- launch
extern "C" void kernel_launch(void* const* d_in, const int* in_sizes, int n_in,
                              void* d_out, int out_size)
{
    const int*   pv = (const int*)d_in[0];
    const int*   qv = (const int*)d_in[1];
    const float* E  = (const float*)d_in[2];
    const float* w1 = (const float*)d_in[3];
    const float* b1 = (const float*)d_in[4];
    const float* w2 = (const float*)d_in[5];
    const float* b2 = (const float*)d_in[6];
    const float* w3 = (const float*)d_in[7];
    const float* b3 = (const float*)d_in[8];
    float* out = (float*)d_out;
    const int M = in_sizes[0];

    static int sms = 0;
    if (sms == 0) {
        cudaDeviceGetAttribute(&sms, cudaDevAttrMultiProcessorCount, 0);
        if (sms <= 0) sms = 148;
        cudaFuncSetAttribute(fused_mlp_mma,
                             cudaFuncAttributeMaxDynamicSharedMemorySize, SMEM_TOTAL);
    }

    pack_w_kernel<<<64, 256>>>(w1, w2);
    int ntiles = (M + TM - 1) / TM;
    int grid = sms < ntiles ? sms : ntiles;
    fused_mlp_mma<<<grid, NTH, SMEM_TOTAL>>>(pv, qv, E, b1, b2, w3, b3, out, M);
}

// round 14
// speedup vs baseline: 1.3232x; 1.3232x over previous
#include <cuda_runtime.h>
#include <cuda_fp16.h>
#include <cstdint>

#define D        256
#define TM       32
#define NTH      128

// smem layout (bytes)
#define SMEM_A     0          // A fp16 row-major: 32 rows x 512B (swizzled) = 16384
#define SMEM_SB1   16384      // 256 floats
#define SMEM_SB2   17408
#define SMEM_SW3   18432
#define SMEM_RED   19456      // 4 x 32 floats
#define SMEM_TOTAL 19968

// frag-packed fp16 weights: [layer(2)][ktile(16)][slot(16)][lane(32)] x 16B
// slot s holds ntiles 2s, 2s+1 (cols 16s..16s+15);
// per lane: {b0(2s), b1(2s), b0(2s+1), b1(2s+1)}
__device__ uint4 g_bpack[2 * 16 * 16 * 32];

__device__ __forceinline__ uint32_t f2h2(float lo, float hi) {
    __half2 h = __floats2half2_rn(lo, hi);
    return *(uint32_t*)&h;
}

__device__ __forceinline__ void mma_f16(float* c, const uint32_t* a, uint32_t b0, uint32_t b1) {
    asm volatile("mma.sync.aligned.m16n8k16.row.col.f32.f16.f16.f32 "
                 "{%0,%1,%2,%3}, {%4,%5,%6,%7}, {%8,%9}, {%0,%1,%2,%3};"
                 : "+f"(c[0]), "+f"(c[1]), "+f"(c[2]), "+f"(c[3])
                 : "r"(a[0]), "r"(a[1]), "r"(a[2]), "r"(a[3]), "r"(b0), "r"(b1));
}

// ------------------------------------------------------------- weight prep
__global__ void pack_w_kernel(const float* __restrict__ w1, const float* __restrict__ w2) {
    int idx = blockIdx.x * 256 + threadIdx.x;      // 16384 uint4 slots
    int l    = idx >> 13;
    int kt   = (idx >> 9) & 15;
    int s    = (idx >> 5) & 15;
    int lane = idx & 31;
    const float* w = l ? w2 : w1;
    int g = lane >> 2, t = lane & 3;
    int k0 = kt * 16 + 2 * t;
    int na = 16 * s + g;
    int nb = na + 8;
    uint4 v;
    v.x = f2h2(w[(k0    ) * D + na], w[(k0 + 1) * D + na]);
    v.y = f2h2(w[(k0 + 8) * D + na], w[(k0 + 9) * D + na]);
    v.z = f2h2(w[(k0    ) * D + nb], w[(k0 + 1) * D + nb]);
    v.w = f2h2(w[(k0 + 8) * D + nb], w[(k0 + 9) * D + nb]);
    g_bpack[idx] = v;
}

// A smem address: row-major fp16, 512B rows, 16B-unit swizzle (low 3 bits ^ row&7)
__device__ __forceinline__ uint32_t a_addr(uint32_t sbA, int row, int unit) {
    return sbA + row * 512 + ((((unsigned)unit & 24u) | (((unsigned)unit ^ (unsigned)(row & 7)) & 7u)) << 4);
}

// ------------------------------------------------------------- main kernel
__global__ __launch_bounds__(NTH, 4)
void fused_mlp_mma(const int* __restrict__ pv, const int* __restrict__ qv,
                   const float* __restrict__ E,
                   const float* __restrict__ b1v, const float* __restrict__ b2v,
                   const float* __restrict__ w3v, const float* __restrict__ b3v,
                   float* __restrict__ out, int M)
{
    extern __shared__ char smem[];
    uint32_t sbA;
    asm("{ .reg .u64 u; cvta.to.shared.u64 u, %1; cvt.u32.u64 %0, u; }" : "=r"(sbA) : "l"(smem));
    const int t = threadIdx.x, lane = t & 31, wn = t >> 5;  // 4 warps, tile 32x64
    const int m0 = blockIdx.x * TM;

    float* sB1 = (float*)(smem + SMEM_SB1);
    float* sB2 = (float*)(smem + SMEM_SB2);
    float* sW3 = (float*)(smem + SMEM_SW3);
    sB1[t] = b1v[t];         sB2[t] = b2v[t];         sW3[t] = w3v[t];
    sB1[t+128] = b1v[t+128]; sB2[t+128] = b2v[t+128]; sW3[t+128] = w3v[t+128];

    // ---- gather + sqdiff -> A rows (fp16): warp-per-row, fully coalesced ----
    {
        int rbase = wn * 8;
        #pragma unroll 4
        for (int rr = 0; rr < 8; ++rr) {
            int r  = rbase + rr;
            int gi = m0 + r;
            int pi = (gi < M) ? __ldg(pv + gi) : 0;
            int qi = (gi < M) ? __ldg(qv + gi) : 0;
            const float4* P = (const float4*)(E + (size_t)pi * D);
            const float4* Q = (const float4*)(E + (size_t)qi * D);
            float4 p0 = __ldg(P + lane), p1 = __ldg(P + 32 + lane);
            float4 q0 = __ldg(Q + lane), q1 = __ldg(Q + 32 + lane);
            float d0 = p0.x - q0.x, d1 = p0.y - q0.y, d2 = p0.z - q0.z, d3 = p0.w - q0.w;
            float e0 = p1.x - q1.x, e1 = p1.y - q1.y, e2 = p1.z - q1.z, e3 = p1.w - q1.w;
            uint32_t lo0 = f2h2(d0 * d0, d1 * d1);
            uint32_t lo1 = f2h2(d2 * d2, d3 * d3);
            uint32_t hi0 = f2h2(e0 * e0, e1 * e1);
            uint32_t hi1 = f2h2(e2 * e2, e3 * e3);
            uint32_t addr0 = a_addr(sbA, r,      lane >> 1) + (lane & 1) * 8;
            uint32_t addr1 = a_addr(sbA, r, 16 + (lane >> 1)) + (lane & 1) * 8;
            asm volatile("st.shared.v2.b32 [%0], {%1,%2};" :: "r"(addr0), "r"(lo0), "r"(lo1));
            asm volatile("st.shared.v2.b32 [%0], {%1,%2};" :: "r"(addr1), "r"(hi0), "r"(hi1));
        }
    }
    __syncthreads();

    float acc[2][8][4];
    #pragma unroll
    for (int m = 0; m < 2; ++m)
        #pragma unroll
        for (int n = 0; n < 8; ++n)
            #pragma unroll
            for (int e = 0; e < 4; ++e) acc[m][n][e] = 0.f;

    // ---- two layers, barrier-free mainloop, B straight from L1/L2 ----------
    #pragma unroll 1
    for (int layer = 0; layer < 2; ++layer) {
        const uint4* bw = g_bpack + (size_t)layer * (16 * 16 * 32);
        uint4 bpre[2][4];                 // 2-deep per-warp B prefetch
        #pragma unroll
        for (int pf = 0; pf < 2; ++pf)
            #pragma unroll
            for (int j = 0; j < 4; ++j)
                bpre[pf][j] = __ldg(bw + ((pf * 16 + wn * 4 + j) * 32 + lane));

        #pragma unroll
        for (int ktl = 0; ktl < 16; ++ktl) {
            uint4 bf[4];
            #pragma unroll
            for (int j = 0; j < 4; ++j) bf[j] = bpre[ktl & 1][j];
            if (ktl + 2 < 16) {
                #pragma unroll
                for (int j = 0; j < 4; ++j)
                    bpre[ktl & 1][j] = __ldg(bw + (((ktl + 2) * 16 + wn * 4 + j) * 32 + lane));
            }
            #pragma unroll
            for (int m = 0; m < 2; ++m) {
                uint32_t a[4];
                int row = m * 16 + (lane & 15);
                uint32_t addr = a_addr(sbA, row, ktl * 2 + (lane >> 4));
                asm volatile("ldmatrix.sync.aligned.m8n8.x4.shared.b16 {%0,%1,%2,%3}, [%4];"
                             : "=r"(a[0]), "=r"(a[1]), "=r"(a[2]), "=r"(a[3])
                             : "r"(addr));
                #pragma unroll
                for (int j = 0; j < 4; ++j) {
                    mma_f16(acc[m][2 * j + 0], a, bf[j].x, bf[j].y);
                    mma_f16(acc[m][2 * j + 1], a, bf[j].z, bf[j].w);
                }
            }
        }

        if (layer == 0) {
            // layer-1 epilogue: acc -> bias+relu -> fp16 A (warp's 64 cols)
            __syncthreads();       // all warps done READING layer-1 A
            #pragma unroll
            for (int m = 0; m < 2; ++m) {
                int r0 = m * 16 + (lane >> 2);
                #pragma unroll
                for (int nt = 0; nt < 8; ++nt) {
                    int c0 = wn * 64 + nt * 8 + 2 * (lane & 3);
                    float v00 = fmaxf(acc[m][nt][0] + sB1[c0],     0.f);
                    float v01 = fmaxf(acc[m][nt][1] + sB1[c0 + 1], 0.f);
                    float v10 = fmaxf(acc[m][nt][2] + sB1[c0],     0.f);
                    float v11 = fmaxf(acc[m][nt][3] + sB1[c0 + 1], 0.f);
                    int u = wn * 8 + nt;
                    int off = (c0 & 7) * 2;
                    *(uint32_t*)(smem + (a_addr(sbA, r0,     u) - sbA) + off) = f2h2(v00, v01);
                    *(uint32_t*)(smem + (a_addr(sbA, r0 + 8, u) - sbA) + off) = f2h2(v10, v11);
                    acc[m][nt][0] = acc[m][nt][1] = acc[m][nt][2] = acc[m][nt][3] = 0.f;
                }
            }
            __syncthreads();       // A rewrite complete before layer-2 reads
        }
    }

    // ---- final: bias+relu, dot w3, reduce ----------------------------------
    {
        float rsum[4];
        #pragma unroll
        for (int k = 0; k < 4; ++k) rsum[k] = 0.f;
        #pragma unroll
        for (int m = 0; m < 2; ++m)
            #pragma unroll
            for (int nt = 0; nt < 8; ++nt)
                #pragma unroll
                for (int h = 0; h < 2; ++h)
                    #pragma unroll
                    for (int e = 0; e < 2; ++e) {
                        int c = wn * 64 + nt * 8 + 2 * (lane & 3) + e;
                        float v = fmaxf(acc[m][nt][h * 2 + e] + sB2[c], 0.f);
                        rsum[m * 2 + h] = fmaf(v, sW3[c], rsum[m * 2 + h]);
                    }
        #pragma unroll
        for (int k = 0; k < 4; ++k) {
            rsum[k] += __shfl_xor_sync(0xffffffffu, rsum[k], 1);
            rsum[k] += __shfl_xor_sync(0xffffffffu, rsum[k], 2);
        }
        float* red = (float*)(smem + SMEM_RED);
        if ((lane & 3) == 0) {
            #pragma unroll
            for (int m = 0; m < 2; ++m)
                #pragma unroll
                for (int h = 0; h < 2; ++h)
                    red[wn * 32 + m * 16 + h * 8 + (lane >> 2)] = rsum[m * 2 + h];
        }
    }
    __syncthreads();
    if (t < TM) {
        int gi = m0 + t;
        float* red = (float*)(smem + SMEM_RED);
        if (gi < M)
            out[gi] = red[t] + red[32 + t] + red[64 + t] + red[96 + t] + __ldg(b3v);
    }
}

// ------------------------------------------------------------- launch
extern "C" void kernel_launch(void* const* d_in, const int* in_sizes, int n_in,
                              void* d_out, int out_size)
{
    const int*   pv = (const int*)d_in[0];
    const int*   qv = (const int*)d_in[1];
    const float* E  = (const float*)d_in[2];
    const float* w1 = (const float*)d_in[3];
    const float* b1 = (const float*)d_in[4];
    const float* w2 = (const float*)d_in[5];
    const float* b2 = (const float*)d_in[6];
    const float* w3 = (const float*)d_in[7];
    const float* b3 = (const float*)d_in[8];
    float* out = (float*)d_out;
    const int M = in_sizes[0];

    cudaFuncSetAttribute(fused_mlp_mma,
                         cudaFuncAttributeMaxDynamicSharedMemorySize, SMEM_TOTAL);

    pack_w_kernel<<<64, 256>>>(w1, w2);
    int grid = (M + TM - 1) / TM;
    fused_mlp_mma<<<grid, NTH, SMEM_TOTAL>>>(pv, qv, E, b1, b2, w3, b3, out, M);
}